// round 7
// baseline (speedup 1.0000x reference)
#include <cuda_runtime.h>
#include <math.h>

#define B 8
#define M 12
#define NN 32
#define D 256
#define C 1024      // N*N
#define CH 512      // C/R
#define BM 96

typedef unsigned long long ull;

// Scratch (allocation-free rule: device globals)
__device__ float g_S[BM * NN];    // row sums per bm
__device__ float g_cov[BM * C];   // centered cov (sign -> mask)
__device__ float g_h[BM * CH];    // hidden after relu
__device__ float g_att[BM * C];   // final attention weights
__device__ int   g_scnt;          // S-ready counter (reset by k3 each run)

// ---- packed f32x2 helpers -------------------------------------------------
__device__ __forceinline__ ull ffma2(ull a, ull b, ull c) {
    ull d_;
    asm("fma.rn.f32x2 %0, %1, %2, %3;" : "=l"(d_) : "l"(a), "l"(b), "l"(c));
    return d_;
}
__device__ __forceinline__ float unpk_add(ull v) {
    float lo, hi;
    asm("mov.b64 {%0, %1}, %2;" : "=f"(lo), "=f"(hi) : "l"(v));
    return lo + hi;
}

// smem swizzle for k2 tiles: q in [0,128) float4 units, chunk = q>>4
#define SWZ(q) (((q) & 0x70) | (((q) ^ ((q) >> 4)) & 0x0F))

#define XPAD 260   // floats per padded x row (= 65 float4): 4-way-max LDS fill
#define RWS  512   // red floats per warp (16 n x 32 k)

// ---------------------------------------------------------------------------
// kA: grid 208, 256 thr.
//  blocks [0,192):   bm = bid>>1, half = bid&1 -> cov rows [half*16, half*16+16).
//                    S computed redundantly per half (half 0 publishes + counts).
//  blocks [192,208): U[n][o] = rowsum+2*colsum-diag of W1 row o (smem only),
//                    spin on S counter, h = relu(U^T S / 512).
// ---------------------------------------------------------------------------
__global__ void __launch_bounds__(256) kA(const float* __restrict__ x,
                                          const float* __restrict__ W1) {
    extern __shared__ float sm[];
    const int tid = threadIdx.x;
    const int w = tid >> 5, lane = tid & 31;

    if (blockIdx.x >= 2 * BM) {
        // ---- U + h blocks: block ub owns o-range [ub*32, ub*32+32) ----
        const int ub = blockIdx.x - 2 * BM;
        float* smT  = sm + w * 1056;     // per-warp 33x32 transpose buf (8448)
        float* U_t  = sm + 8448;         // [n*33 + o_local], 1056
        float* S_sm = sm + 9504;         // 96x32 = 3072

        #pragma unroll
        for (int i = 0; i < 4; i++) {
            const int ol = w * 4 + i;
            const int o  = ub * 32 + ol;
            const float* row = W1 + (size_t)o * C;
            float r[32], cs = 0.f;
            #pragma unroll
            for (int j = 0; j < 32; j++) { r[j] = row[j * 32 + lane]; cs += r[j]; }
            #pragma unroll
            for (int j = 0; j < 32; j++) smT[j * 33 + lane] = r[j];
            __syncwarp();
            float rs = 0.f;
            #pragma unroll
            for (int mm = 0; mm < 32; mm++) rs += smT[lane * 33 + mm];
            const float dg = smT[lane * 33 + lane];
            U_t[lane * 33 + ol] = rs + 2.f * cs - dg;   // lane = n
            __syncwarp();
        }
        __syncthreads();

        if (tid == 0) { while (atomicAdd(&g_scnt, 0) < BM) { } }
        __syncthreads();
        __threadfence();

        for (int i = tid; i < BM * NN; i += 256) S_sm[i] = g_S[i];
        __syncthreads();

        const int ol = lane;             // o local
        float u[32];
        #pragma unroll
        for (int n = 0; n < NN; n++) u[n] = U_t[n * 33 + ol];

        #pragma unroll
        for (int bmi = 0; bmi < 12; bmi++) {
            const int bm = w * 12 + bmi;
            float acc = 0.f;
            #pragma unroll
            for (int n = 0; n < NN; n++) acc += u[n] * S_sm[bm * 32 + n];
            g_h[(size_t)bm * CH + ub * 32 + ol] = fmaxf(acc * (1.f / 512.f), 0.f);
        }
        return;
    }

    // ---- bm half blocks ----
    const int bm = blockIdx.x >> 1;
    const int half = blockIdx.x & 1;
    float* xs  = sm;                 // padded natural [n*XPAD + d], 8320
    float* red = sm + 8320;          // 8 x 512 partials
    float* sp  = sm + 8320 + 8 * RWS;
    float* S   = sp + 256;

    const float4* xg4 = (const float4*)(x + (size_t)bm * (NN * D));
    float4* xs4 = (float4*)xs;
    #pragma unroll
    for (int t = 0; t < 8; t++) {
        const int i = tid + t * 256;
        const int n = i >> 6, q = i & 63;
        xs4[n * 65 + q] = xg4[i];    // conflict-free STS.128
    }
    __syncthreads();

    // register fill: xk = x[k=lane][w*32 .. w*32+31], packed pairs.
    // LDS.64 from padded rows: banks 4*lane mod 32 -> ~4-way, cheap.
    ull xk2[16];
    float spv = 0.f;
    const float* xrow = xs + lane * XPAD + w * 32;
    #pragma unroll
    for (int j = 0; j < 16; j++) {
        const ull v = *(const ull*)(xrow + 2 * j);
        xk2[j] = v;
        float lo, hi;
        asm("mov.b64 {%0, %1}, %2;" : "=f"(lo), "=f"(hi) : "l"(v));
        spv += lo + hi;
    }
    sp[w * 32 + lane] = spv;
    __syncthreads();
    if (tid < 32) {
        float s = 0.f;
        #pragma unroll
        for (int ww = 0; ww < 8; ww++) s += sp[ww * 32 + tid];
        S[tid] = s;
        if (half == 0) { g_S[bm * 32 + tid] = s; __threadfence(); }
    }
    __syncthreads();
    if (half == 0 && tid == 0) atomicAdd(&g_scnt, 1);

    // cov partials for n in [half*16, half*16+16)
    const int n0 = half * 16;
    ull acc2[16];
    #pragma unroll
    for (int nn = 0; nn < 16; nn++) acc2[nn] = 0ull;

    const ulonglong2* xs2 = (const ulonglong2*)xs;   // rows stride 65 f4
    #pragma unroll
    for (int nn = 0; nn < 16; nn++) {
        const ulonglong2* rowp = xs2 + (n0 + nn) * 65 + w * 8;
        #pragma unroll
        for (int jj = 0; jj < 8; jj++) {
            const ulonglong2 bv = rowp[jj];          // broadcast LDS.128
            acc2[nn] = ffma2(bv.x, xk2[2 * jj], acc2[nn]);
            acc2[nn] = ffma2(bv.y, xk2[2 * jj + 1], acc2[nn]);
        }
    }

    #pragma unroll
    for (int nn = 0; nn < 16; nn++) red[w * RWS + nn * 32 + lane] = unpk_add(acc2[nn]);
    __syncthreads();

    if (tid < 128) {   // combine 8 warp-partials, subtract S_n S_k / 256
        const float4* red4 = (const float4*)red;
        float4 cv = make_float4(0.f, 0.f, 0.f, 0.f);
        #pragma unroll
        for (int ww = 0; ww < 8; ww++) {
            const float4 t = red4[ww * 128 + tid];
            cv.x += t.x; cv.y += t.y; cv.z += t.z; cv.w += t.w;
        }
        const int n = n0 + (tid >> 3), k0 = (tid & 7) * 4;
        const float sn = S[n] * (1.f / 256.f);
        cv.x -= sn * S[k0 + 0]; cv.y -= sn * S[k0 + 1];
        cv.z -= sn * S[k0 + 2]; cv.w -= sn * S[k0 + 3];
        ((float4*)(g_cov + (size_t)bm * C + n0 * NN))[tid] = cv;
    }
}

// ---------------------------------------------------------------------------
// k2: grid (16 ct, 8 b), 256 thr. W2 tile (64x512) + h (12x512) staged in
// swizzled smem; thread (c2, kc) serves all 12 m per W2 load (12x reuse).
// Fused sigmoid + mask + warp softmax; writes final att rows 2ct, 2ct+1.
// ---------------------------------------------------------------------------
__global__ void __launch_bounds__(256) k2_gemm_softmax(const float* __restrict__ W2) {
    extern __shared__ float s2[];
    const int ct = blockIdx.x, b = blockIdx.y;
    const int tid = threadIdx.x;
    const int w = tid >> 5, lane = tid & 31;

    {
        float4* W2s = (float4*)s2;                  // 8192 float4
        const float4* w2g = (const float4*)(W2 + (size_t)(ct * 64) * CH);
        #pragma unroll
        for (int t = 0; t < 32; t++) {
            const int i = tid + t * 256;
            const int c = i >> 7, q = i & 127;
            W2s[c * 128 + SWZ(q)] = w2g[i];
        }
        float4* hsv = (float4*)(s2 + 32768);        // 1536 float4
        const float4* hg = (const float4*)(g_h + (size_t)b * M * CH);
        #pragma unroll
        for (int t = 0; t < 6; t++) {
            const int i = tid + t * 256;
            const int m = i >> 7, q = i & 127;
            hsv[m * 128 + SWZ(q)] = hg[i];
        }
    }
    __syncthreads();

    const int c2 = tid >> 3;          // 0..31 -> rows 2c2, 2c2+1
    const int kc = tid & 7;           // k-chunk of 64 floats
    const int cA = 2 * c2, cB = 2 * c2 + 1;

    ull acc0[12], acc1[12];
    #pragma unroll
    for (int m = 0; m < 12; m++) { acc0[m] = 0ull; acc1[m] = 0ull; }

    const ulonglong2* W2u = (const ulonglong2*)s2;
    const ulonglong2* hu  = (const ulonglong2*)(s2 + 32768);
    const int kc16 = kc * 16;

    #pragma unroll 4
    for (int j = 0; j < 16; j++) {
        const int qs = kc16 + ((j ^ kc) & 15);
        const ulonglong2 wa = W2u[cA * 128 + qs];
        const ulonglong2 wb = W2u[cB * 128 + qs];
        #pragma unroll
        for (int m = 0; m < 12; m++) {
            const ulonglong2 hv = hu[m * 128 + qs];
            acc0[m] = ffma2(wa.x, hv.x, acc0[m]);
            acc0[m] = ffma2(wa.y, hv.y, acc0[m]);
            acc1[m] = ffma2(wb.x, hv.x, acc1[m]);
            acc1[m] = ffma2(wb.y, hv.y, acc1[m]);
        }
    }
    __syncthreads();   // done with staged tiles; reuse s2

    float* part  = s2;                // [kc][c*12+m], stride 771
    float* ev_sm = s2 + 8 * 771;      // [c][m], stride 13

    #pragma unroll
    for (int m = 0; m < 12; m++) {
        part[kc * 771 + cA * 12 + m] = unpk_add(acc0[m]);
        part[kc * 771 + cB * 12 + m] = unpk_add(acc1[m]);
    }
    __syncthreads();

    #pragma unroll
    for (int t = 0; t < 3; t++) {
        const int idx = tid + t * 256;        // = c*12 + m
        const int c = idx / 12, m = idx - 12 * c;
        float e2v = 0.f;
        #pragma unroll
        for (int kk = 0; kk < 8; kk++) e2v += part[kk * 771 + idx];
        const int bm = b * M + m;
        const float cv = g_cov[(size_t)bm * C + ct * 64 + c];
        const float sg = 1.f / (1.f + __expf(-e2v));
        ev_sm[c * 13 + m] = (cv > 0.f) ? __expf(sg) : 0.f;
    }
    __syncthreads();

    #pragma unroll
    for (int it = 0; it < 3; it++) {
        const int p = it * 8 + w;             // 0..23
        const int n = p / 12, m = p - 12 * n;
        const float v = ev_sm[(n * 32 + lane) * 13 + m];
        float s = v;
        #pragma unroll
        for (int off = 16; off; off >>= 1) s += __shfl_xor_sync(0xffffffffu, s, off);
        g_att[(size_t)(b * M + m) * C + (ct * 2 + n) * NN + lane] = v / s;
    }
}

// ---------------------------------------------------------------------------
// k3: per bm, 256 thr. Pure AV: out[n][d=tid] = sum_k att[n][k] * x[k][d].
// Also resets g_scnt for the next graph replay.
// ---------------------------------------------------------------------------
__global__ void __launch_bounds__(256) k3_av(const float* __restrict__ x,
                                             float* __restrict__ out) {
    const int bm = blockIdx.x;
    __shared__ float xs[NN * D];   // 32 KB
    __shared__ float att[C];       // 4 KB

    if (blockIdx.x == 0 && threadIdx.x == 0) atomicExch(&g_scnt, 0);

    const int tid = threadIdx.x;
    const float4* xg4 = (const float4*)(x + (size_t)bm * (NN * D));
    float4* xs4 = (float4*)xs;
    #pragma unroll
    for (int i = 0; i < 8; i++) xs4[tid + i * 256] = xg4[tid + i * 256];

    ((float4*)att)[tid] = ((const float4*)(g_att + (size_t)bm * C))[tid];
    __syncthreads();

    ull xv2[16];
    #pragma unroll
    for (int kk = 0; kk < 16; kk++)
        xv2[kk] = *(const ull*)(xs + (2 * kk) * D + tid) * 0 + 0;  // placeholder避免
    // NOTE: the above would be wrong (non-adjacent); build pairs explicitly:
    #pragma unroll
    for (int kk = 0; kk < 16; kk++) {
        ull r;
        asm("mov.b64 %0, {%1, %2};" : "=l"(r)
            : "f"(xs[(2 * kk) * D + tid]), "f"(xs[(2 * kk + 1) * D + tid]));
        xv2[kk] = r;
    }

    float* ot = out + (size_t)bm * (NN * D);
    #pragma unroll 4
    for (int n = 0; n < NN; n++) {
        const ulonglong2* ar = (const ulonglong2*)(att + n * NN);
        ull a2 = 0ull;
        #pragma unroll
        for (int jj = 0; jj < 8; jj++) {
            const ulonglong2 bv = ar[jj];        // broadcast LDS.128
            a2 = ffma2(bv.x, xv2[2 * jj], a2);
            a2 = ffma2(bv.y, xv2[2 * jj + 1], a2);
        }
        ot[n * D + tid] = unpk_add(a2);
    }
}

// ---------------------------------------------------------------------------
extern "C" void kernel_launch(void* const* d_in, const int* in_sizes, int n_in,
                              void* d_out, int out_size) {
    const float* x  = (const float*)d_in[0];
    const float* W1 = (const float*)d_in[1];
    const float* W2 = (const float*)d_in[2];
    float* out = (float*)d_out;

    const int smemA = (8320 + 8 * RWS + 256 + 32) * sizeof(float);  // 50,976 B
    const int smemB = (32768 + 6144) * sizeof(float);               // 155,648 B
    cudaFuncSetAttribute(kA, cudaFuncAttributeMaxDynamicSharedMemorySize, smemA);
    cudaFuncSetAttribute(k2_gemm_softmax, cudaFuncAttributeMaxDynamicSharedMemorySize, smemB);

    kA<<<2 * BM + 16, 256, smemA>>>(x, W1);
    k2_gemm_softmax<<<dim3(16, B), 256, smemB>>>(W2);
    k3_av<<<BM, 256>>>(x, out);
}